// round 16
// baseline (speedup 1.0000x reference)
#include <cuda_runtime.h>
#include <cuda_bf16.h>

#define L1N 16
#define DIN 1536
#define KHALF 768
#define COUNT 8
#define L3N 64
#define BMAX 16384
#define CTA_SAMPLES 128
#define THREADS 256
#define CK 32                   // k per chunk (per half)
#define NCH (KHALF / CK)        // 24
#define XST 36                  // x smem row stride
#define RST 20                  // reduction row stride
#define HB 64
#define NSTAGE 3
#define MAXSLOT (BMAX + COUNT * CTA_SAMPLES)

// ---- device scratch ----
__device__ float g_wsum[COUNT * DIN * L1N];   // [b][k][16]
__device__ float g_bsum[COUNT * L1N];
__device__ float g_w2p[COUNT * L3N * 32];
__device__ float g_part[MAXSLOT * 32];        // [slot][half*16 + o]  (SLOT-indexed!)
__device__ int   g_bh[HB * COUNT];
__device__ int   g_aoff[COUNT + 1];
__device__ int   g_order[MAXSLOT];

// ---------------- prep: transpose W1+Wf, pad W2, per-block hist ----------------
__global__ void k_prep(const float* __restrict__ W1, const float* __restrict__ b1,
                       const float* __restrict__ Wf, const float* __restrict__ bf,
                       const float* __restrict__ W2, const int* __restrict__ ls,
                       int n, int hb) {
    __shared__ float tile[16 * 20];
    int t = threadIdx.x;
    int bucket = blockIdx.x / 96;
    int kt = blockIdx.x - bucket * 96;   // 16-k tile

    {
        int row = t >> 4;
        int col = t & 15;
        tile[row * 20 + col] = W1[(size_t)(bucket * L1N + row) * DIN + kt * 16 + col]
                             + Wf[(size_t)row * DIN + kt * 16 + col];
    }
    __syncthreads();
    if (t < 64) {
        float4* dst = (float4*)(g_wsum + (size_t)bucket * (DIN * L1N));
        int k = t >> 2;
        int o4 = t & 3;
        float4 v;
        v.x = tile[(4 * o4 + 0) * 20 + k];
        v.y = tile[(4 * o4 + 1) * 20 + k];
        v.z = tile[(4 * o4 + 2) * 20 + k];
        v.w = tile[(4 * o4 + 3) * 20 + k];
        dst[(kt * 16 + k) * 4 + o4] = v;
    }

    int tidg = blockIdx.x * 256 + t;
    if (tidg < COUNT * L3N * 32) {
        int b = tidg >> 11;
        int j = (tidg >> 5) & 63;
        int i = tidg & 31;
        g_w2p[tidg] = (i < 30) ? W2[(b * L3N + j) * 30 + i] : 0.0f;
    }
    if (tidg < COUNT * L1N) {
        int b = tidg >> 4, o = tidg & 15;
        g_bsum[tidg] = b1[b * L1N + o] + bf[o];
    }
    if ((int)blockIdx.x < hb) {
        __shared__ int sh[COUNT];
        if (t < COUNT) sh[t] = 0;
        __syncthreads();
        int i = blockIdx.x * 256 + t;
        if (i < n) {
            int b = ls[i];
            unsigned act = __activemask();
            unsigned m = __match_any_sync(act, b);
            int lane = t & 31;
            int leader = __ffs(m) - 1;
            if (lane == leader) atomicAdd(&sh[b], __popc(m));
        }
        __syncthreads();
        if (t < COUNT) g_bh[blockIdx.x * COUNT + t] = sh[t];
    }
}

// ---------------- scatter with inline scan ----------------
__global__ void k_scatter(const int* __restrict__ ls, int n, int hb) {
    __shared__ int sh[HB * COUNT];
    __shared__ int s_aoff[COUNT + 1];
    __shared__ int s_cnt[COUNT];
    __shared__ int cur[COUNT];
    int t = threadIdx.x;
    for (int i = t; i < hb * COUNT; i += 256) sh[i] = g_bh[i];
    __syncthreads();
    if (t < COUNT) {
        int tot = 0;
        for (int j = 0; j < hb; ++j) tot += sh[j * COUNT + t];
        s_cnt[t] = tot;
    }
    __syncthreads();
    if (t == 0) {
        int off = 0;
        for (int b = 0; b < COUNT; ++b) {
            s_aoff[b] = off;
            off += (s_cnt[b] + CTA_SAMPLES - 1) & ~(CTA_SAMPLES - 1);
        }
        s_aoff[COUNT] = off;
        if (blockIdx.x == 0)
            for (int b = 0; b <= COUNT; ++b) g_aoff[b] = s_aoff[b];
    }
    __syncthreads();
    if (t < COUNT) {
        int run = s_aoff[t];
        for (int j = 0; j < (int)blockIdx.x; ++j) run += sh[j * COUNT + t];
        cur[t] = run;
    }
    __syncthreads();
    if (blockIdx.x == 0) {
        for (int b = 0; b < COUNT; ++b) {
            int s = s_aoff[b] + s_cnt[b];
            int e = s_aoff[b + 1];
            for (int i = s + t; i < e; i += 256) g_order[i] = -1;
        }
    }
    int i = blockIdx.x * 256 + t;
    if (i < n) {
        int b = ls[i];
        unsigned act = __activemask();
        unsigned m = __match_any_sync(act, b);
        int lane = t & 31;
        int leader = __ffs(m) - 1;
        int rank = __popc(m & ((1u << lane) - 1u));
        int base = 0;
        if (lane == leader) base = atomicAdd(&cur[b], __popc(m));
        base = __shfl_sync(act, base, leader);
        g_order[base + rank] = i;
    }
}

// ---------------- main: split-K, 256 thr, 4 samples/lane, 2 CTAs/SM ----------------
#define XBUF_WORDS (128 * XST)
#define SIDX_OFF (12288 + NSTAGE * XBUF_WORDS)     // 26112
#define SMEM_WORDS (SIDX_OFF + 128)                // 26240
#define SMEM_BYTES (SMEM_WORDS * 4)

__device__ __forceinline__ unsigned smem_u32(const void* p) {
    unsigned a;
    asm("{ .reg .u64 t; cvta.to.shared.u64 t, %1; cvt.u32.u64 %0, t; }" : "=r"(a) : "l"(p));
    return a;
}

__global__ void __launch_bounds__(THREADS, 2) k_main(const float* __restrict__ x) {
    extern __shared__ float sm[];
    float* ws   = sm;
    float* xs   = ws + 12288;
    int* sidx_s = (int*)(sm + SIDX_OFF);

    int tid = threadIdx.x;
    int base = blockIdx.x * CTA_SAMPLES;
    int kh = blockIdx.y;
    if (base >= g_aoff[COUNT]) return;

    int b = 0;
#pragma unroll
    for (int t = 1; t < COUNT; ++t)
        if (base >= g_aoff[t]) b = t;

    if (tid < 128) sidx_s[tid] = g_order[base + tid];
    __syncthreads();

    const char* gsrc[4];
    unsigned dsmem[4];
    unsigned xs_u = smem_u32(xs);
#pragma unroll
    for (int r = 0; r < 4; ++r) {
        int idx = tid + THREADS * r;
        int s = idx >> 3;
        int k4 = idx & 7;
        int sv = sidx_s[s];
        gsrc[r] = (const char*)(x + (size_t)(sv >= 0 ? sv : 0) * DIN + kh * KHALF + k4 * 4);
        dsmem[r] = xs_u + (unsigned)((s * XST + k4 * 4) * 4);
    }
#define ISSUE_CHUNK(c)                                                              \
    do {                                                                            \
        unsigned boff = (unsigned)(((c) % NSTAGE) * XBUF_WORDS * 4);                \
        _Pragma("unroll")                                                           \
        for (int r = 0; r < 4; ++r)                                                 \
            asm volatile("cp.async.cg.shared.global [%0], [%1], 16;"                \
                         :: "r"(dsmem[r] + boff), "l"(gsrc[r] + (size_t)(c) * 128)); \
        asm volatile("cp.async.commit_group;");                                     \
    } while (0)

    ISSUE_CHUNK(0);
    ISSUE_CHUNK(1);

    {
        const float4* src = (const float4*)(g_wsum + (size_t)b * (DIN * L1N) + (size_t)kh * KHALF * L1N);
        float4* dst = (float4*)ws;
#pragma unroll
        for (int r = 0; r < 12; ++r) dst[tid + r * THREADS] = src[tid + r * THREADS];
    }

    int wid = tid >> 5, lane = tid & 31;

    unsigned long long acc[32];
#pragma unroll
    for (int i = 0; i < 32; ++i) acc[i] = 0ULL;

    const ulonglong2* wp = (const ulonglong2*)ws;

#pragma unroll 1
    for (int c = 0; c < NCH; ++c) {
        if (c + 1 < NCH) asm volatile("cp.async.wait_group 1;");
        else             asm volatile("cp.async.wait_group 0;");
        __syncthreads();
        if (c + 2 < NCH) ISSUE_CHUNK(c + 2);

        const float* xb = xs + (c % NSTAGE) * XBUF_WORDS;
        float4 xa[4];
#pragma unroll
        for (int r = 0; r < 4; ++r)
            xa[r] = *(const float4*)(xb + (lane + 32 * r) * XST + wid * 4);
        int kg = c * CK + wid * 4;
#pragma unroll
        for (int t4 = 0; t4 < 4; ++t4) {
            const ulonglong2* wr = wp + (unsigned)(kg + t4) * 4;
            ulonglong2 w0 = wr[0], w1 = wr[1], w2 = wr[2], w3 = wr[3];
#pragma unroll
            for (int r = 0; r < 4; ++r) {
                float v = (t4 == 0) ? xa[r].x : (t4 == 1) ? xa[r].y
                        : (t4 == 2) ? xa[r].z : xa[r].w;
                unsigned long long d;
                asm("mov.b64 %0, {%1, %1};" : "=l"(d) : "f"(v));
                unsigned long long* a = acc + r * 8;
                asm("fma.rn.f32x2 %0, %1, %2, %0;" : "+l"(a[0]) : "l"(d), "l"(w0.x));
                asm("fma.rn.f32x2 %0, %1, %2, %0;" : "+l"(a[1]) : "l"(d), "l"(w0.y));
                asm("fma.rn.f32x2 %0, %1, %2, %0;" : "+l"(a[2]) : "l"(d), "l"(w1.x));
                asm("fma.rn.f32x2 %0, %1, %2, %0;" : "+l"(a[3]) : "l"(d), "l"(w1.y));
                asm("fma.rn.f32x2 %0, %1, %2, %0;" : "+l"(a[4]) : "l"(d), "l"(w2.x));
                asm("fma.rn.f32x2 %0, %1, %2, %0;" : "+l"(a[5]) : "l"(d), "l"(w2.y));
                asm("fma.rn.f32x2 %0, %1, %2, %0;" : "+l"(a[6]) : "l"(d), "l"(w3.x));
                asm("fma.rn.f32x2 %0, %1, %2, %0;" : "+l"(a[7]) : "l"(d), "l"(w3.y));
            }
        }
    }
    __syncthreads();

    // 8-slice reduction in smem overlay (words 0..20479; sidx at 26112 safe)
    float* red = sm;
    {
#pragma unroll
        for (int r = 0; r < 4; ++r) {
            int s = lane + 32 * r;
            float* br = red + (wid * 128 + s) * RST;
#pragma unroll
            for (int p = 0; p < 4; ++p) {
                float lo0, hi0, lo1, hi1;
                asm("mov.b64 {%0, %1}, %2;" : "=f"(lo0), "=f"(hi0) : "l"(acc[r * 8 + 2 * p]));
                asm("mov.b64 {%0, %1}, %2;" : "=f"(lo1), "=f"(hi1) : "l"(acc[r * 8 + 2 * p + 1]));
                *(float4*)(br + 4 * p) = make_float4(lo0, hi0, lo1, hi1);
            }
        }
    }
    __syncthreads();

    // combine + write partials by SLOT (fully coalesced)
    {
        int s = tid >> 1;
        int oc = (tid & 1) * 8;
        float4 v0 = make_float4(0.f, 0.f, 0.f, 0.f);
        float4 v1 = v0;
#pragma unroll
        for (int q = 0; q < 8; ++q) {
            const float* rr = red + (q * 128 + s) * RST + oc;
            float4 a = *(const float4*)(rr);
            float4 c = *(const float4*)(rr + 4);
            v0.x += a.x; v0.y += a.y; v0.z += a.z; v0.w += a.w;
            v1.x += c.x; v1.y += c.y; v1.z += c.z; v1.w += c.w;
        }
        float* dst = g_part + (size_t)(base + s) * 32 + kh * 16 + oc;
        *(float4*)dst = v0;
        *(float4*)(dst + 4) = v1;
    }
}

// ---------------- tail v5: 272 blocks x 512 thr; block=(tile,half) -> 64 samples, 8 j/thread ----------------
__global__ void __launch_bounds__(512) k_tail(const float* __restrict__ b2,
                                              const float* __restrict__ Wo,
                                              const float* __restrict__ bo,
                                              float* __restrict__ out) {
    __shared__ float w2s[2048];
    __shared__ float bs2[16];
    __shared__ float b2s[64];
    __shared__ float wos[64];
    __shared__ float red2[512];
    __shared__ int sidx_s[64];

    int tid = threadIdx.x;
    int tileId = blockIdx.x >> 1;
    int kh = blockIdx.x & 1;
    int base = tileId * CTA_SAMPLES;
    if (base >= g_aoff[COUNT]) return;

    int b = 0;
#pragma unroll
    for (int t = 1; t < COUNT; ++t)
        if (base >= g_aoff[t]) b = t;

    ((float4*)w2s)[tid] = ((const float4*)(g_w2p + (size_t)b * (L3N * 32)))[tid];
    if (tid < 16) bs2[tid] = g_bsum[b * L1N + tid];
    else if (tid >= 32 && tid < 96) b2s[tid - 32] = b2[b * L3N + (tid - 32)];
    else if (tid >= 96 && tid < 160) wos[tid - 96] = Wo[b * L3N + (tid - 96)];
    if (tid < 64) sidx_s[tid] = g_order[base + kh * 64 + tid];
    __syncthreads();

    int s2 = tid & 63;        // local sample within this half
    int jg = tid >> 6;        // 8 j-groups of 8

    // partials: SLOT-indexed -> coalesced
    const float* psafe = g_part + (size_t)(base + kh * 64 + s2) * 32;

    float l1[16];
#pragma unroll
    for (int o = 0; o < 16; o += 4) {
        float4 a = *(const float4*)(psafe + o);
        float4 c = *(const float4*)(psafe + 16 + o);
        l1[o]     = bs2[o]     + a.x + c.x;
        l1[o + 1] = bs2[o + 1] + a.y + c.y;
        l1[o + 2] = bs2[o + 2] + a.z + c.z;
        l1[o + 3] = bs2[o + 3] + a.w + c.w;
    }

    const float C = 127.0f / 128.0f;
    float lx[32];
#pragma unroll
    for (int i = 0; i < 15; ++i) {
        float v = l1[i];
        float sq = (v * v) * C;
        lx[i]      = fminf(fmaxf(sq, 0.0f), 1.0f);
        lx[15 + i] = fminf(fmaxf(v, 0.0f), 1.0f);
    }
    lx[30] = 0.0f;
    lx[31] = 0.0f;

    float l3p = 0.0f;
#pragma unroll
    for (int jj = 0; jj < 8; jj += 2) {
        int j = jg * 8 + jj;
        const float4* wrA = (const float4*)(w2s + j * 32);
        const float4* wrB = (const float4*)(w2s + (j + 1) * 32);
        float sA0 = b2s[j], sA1 = 0.0f;
        float sB0 = b2s[j + 1], sB1 = 0.0f;
#pragma unroll
        for (int p = 0; p < 8; p += 2) {
            float4 a0 = wrA[p], a1 = wrA[p + 1];
            float4 c0 = wrB[p], c1 = wrB[p + 1];
            sA0 = fmaf(lx[4*p+0], a0.x, sA0); sA0 = fmaf(lx[4*p+1], a0.y, sA0);
            sA0 = fmaf(lx[4*p+2], a0.z, sA0); sA0 = fmaf(lx[4*p+3], a0.w, sA0);
            sA1 = fmaf(lx[4*p+4], a1.x, sA1); sA1 = fmaf(lx[4*p+5], a1.y, sA1);
            sA1 = fmaf(lx[4*p+6], a1.z, sA1); sA1 = fmaf(lx[4*p+7], a1.w, sA1);
            sB0 = fmaf(lx[4*p+0], c0.x, sB0); sB0 = fmaf(lx[4*p+1], c0.y, sB0);
            sB0 = fmaf(lx[4*p+2], c0.z, sB0); sB0 = fmaf(lx[4*p+3], c0.w, sB0);
            sB1 = fmaf(lx[4*p+4], c1.x, sB1); sB1 = fmaf(lx[4*p+5], c1.y, sB1);
            sB1 = fmaf(lx[4*p+6], c1.z, sB1); sB1 = fmaf(lx[4*p+7], c1.w, sB1);
        }
        float scA = fminf(fmaxf(sA0 + sA1, 0.0f), 1.0f);
        float scB = fminf(fmaxf(sB0 + sB1, 0.0f), 1.0f);
        l3p = fmaf(scA, wos[j], l3p);
        l3p = fmaf(scB, wos[j + 1], l3p);
    }
    red2[jg * 64 + s2] = l3p;
    __syncthreads();

    if (tid < 64) {
        int sv = sidx_s[tid];
        if (sv >= 0) {
            float l3 = 0.0f;
#pragma unroll
            for (int q = 0; q < 8; ++q) l3 += red2[q * 64 + tid];
            out[sv] = l3 + bo[b] + l1[15];
        }
    }
}

// ---------------- launch ----------------
extern "C" void kernel_launch(void* const* d_in, const int* in_sizes, int n_in,
                              void* d_out, int out_size) {
    const float* x  = (const float*)d_in[0];
    const int*   ls = (const int*)d_in[1];
    const float* W1 = (const float*)d_in[2];
    const float* b1 = (const float*)d_in[3];
    const float* Wf = (const float*)d_in[4];
    const float* bf = (const float*)d_in[5];
    const float* W2 = (const float*)d_in[6];
    const float* b2 = (const float*)d_in[7];
    const float* Wo = (const float*)d_in[8];
    const float* bo = (const float*)d_in[9];
    float* out = (float*)d_out;
    int n = in_sizes[1];
    if (n > BMAX) n = BMAX;

    cudaFuncSetAttribute(k_main, cudaFuncAttributeMaxDynamicSharedMemorySize, SMEM_BYTES);

    int hb = (n + 255) / 256;
    k_prep<<<768, 256>>>(W1, b1, Wf, bf, W2, ls, n, hb);
    k_scatter<<<hb, 256>>>(ls, n, hb);

    int nblk = (n + CTA_SAMPLES - 1) / CTA_SAMPLES + COUNT;
    dim3 grid(nblk, 2);
    k_main<<<grid, THREADS, SMEM_BYTES>>>(x);
    k_tail<<<nblk * 2, 512>>>(b2, Wo, bo, out);
}

// round 17
// speedup vs baseline: 1.1770x; 1.1770x over previous
#include <cuda_runtime.h>
#include <cuda_bf16.h>

#define L1N 16
#define DIN 1536
#define COUNT 8
#define L3N 64
#define BMAX 16384
#define CTA_S 64                // samples per CTA
#define THREADS 256
#define CK 32                   // k per chunk
#define NCHF (DIN / CK)         // 48 chunks full-K
#define WSUB 24                 // chunks per 48KB weight sub-block
#define XST 36                  // x smem row stride
#define RST 20                  // reduction row stride
#define HB 64
#define NSTAGE 3
#define MAXSLOT (BMAX + COUNT * CTA_S)

// ---- device scratch ----
__device__ float g_wsum[COUNT * DIN * L1N];   // [b][k][16]
__device__ float g_bsum[COUNT * L1N];
__device__ float g_w2p[COUNT * L3N * 32];
__device__ int   g_bh[HB * COUNT];
__device__ int   g_aoff[COUNT + 1];
__device__ int   g_order[MAXSLOT];

// ---------------- prep: transpose W1+Wf, pad W2, per-block hist ----------------
__global__ void k_prep(const float* __restrict__ W1, const float* __restrict__ b1,
                       const float* __restrict__ Wf, const float* __restrict__ bf,
                       const float* __restrict__ W2, const int* __restrict__ ls,
                       int n, int hb) {
    __shared__ float tile[16 * 20];
    int t = threadIdx.x;
    int bucket = blockIdx.x / 96;
    int kt = blockIdx.x - bucket * 96;   // 16-k tile

    {
        int row = t >> 4;
        int col = t & 15;
        tile[row * 20 + col] = W1[(size_t)(bucket * L1N + row) * DIN + kt * 16 + col]
                             + Wf[(size_t)row * DIN + kt * 16 + col];
    }
    __syncthreads();
    if (t < 64) {
        float4* dst = (float4*)(g_wsum + (size_t)bucket * (DIN * L1N));
        int k = t >> 2;
        int o4 = t & 3;
        float4 v;
        v.x = tile[(4 * o4 + 0) * 20 + k];
        v.y = tile[(4 * o4 + 1) * 20 + k];
        v.z = tile[(4 * o4 + 2) * 20 + k];
        v.w = tile[(4 * o4 + 3) * 20 + k];
        dst[(kt * 16 + k) * 4 + o4] = v;
    }

    int tidg = blockIdx.x * 256 + t;
    if (tidg < COUNT * L3N * 32) {
        int b = tidg >> 11;
        int j = (tidg >> 5) & 63;
        int i = tidg & 31;
        g_w2p[tidg] = (i < 30) ? W2[(b * L3N + j) * 30 + i] : 0.0f;
    }
    if (tidg < COUNT * L1N) {
        int b = tidg >> 4, o = tidg & 15;
        g_bsum[tidg] = b1[b * L1N + o] + bf[o];
    }
    if ((int)blockIdx.x < hb) {
        __shared__ int sh[COUNT];
        if (t < COUNT) sh[t] = 0;
        __syncthreads();
        int i = blockIdx.x * 256 + t;
        if (i < n) {
            int b = ls[i];
            unsigned act = __activemask();
            unsigned m = __match_any_sync(act, b);
            int lane = t & 31;
            int leader = __ffs(m) - 1;
            if (lane == leader) atomicAdd(&sh[b], __popc(m));
        }
        __syncthreads();
        if (t < COUNT) g_bh[blockIdx.x * COUNT + t] = sh[t];
    }
}

// ---------------- scatter with inline scan (64-padding) ----------------
__global__ void k_scatter(const int* __restrict__ ls, int n, int hb) {
    __shared__ int sh[HB * COUNT];
    __shared__ int s_aoff[COUNT + 1];
    __shared__ int s_cnt[COUNT];
    __shared__ int cur[COUNT];
    int t = threadIdx.x;
    for (int i = t; i < hb * COUNT; i += 256) sh[i] = g_bh[i];
    __syncthreads();
    if (t < COUNT) {
        int tot = 0;
        for (int j = 0; j < hb; ++j) tot += sh[j * COUNT + t];
        s_cnt[t] = tot;
    }
    __syncthreads();
    if (t == 0) {
        int off = 0;
        for (int b = 0; b < COUNT; ++b) {
            s_aoff[b] = off;
            off += (s_cnt[b] + CTA_S - 1) & ~(CTA_S - 1);
        }
        s_aoff[COUNT] = off;
        if (blockIdx.x == 0)
            for (int b = 0; b <= COUNT; ++b) g_aoff[b] = s_aoff[b];
    }
    __syncthreads();
    if (t < COUNT) {
        int run = s_aoff[t];
        for (int j = 0; j < (int)blockIdx.x; ++j) run += sh[j * COUNT + t];
        cur[t] = run;
    }
    __syncthreads();
    if (blockIdx.x == 0) {
        for (int b = 0; b < COUNT; ++b) {
            int s = s_aoff[b] + s_cnt[b];
            int e = s_aoff[b + 1];
            for (int i = s + t; i < e; i += 256) g_order[i] = -1;
        }
    }
    int i = blockIdx.x * 256 + t;
    if (i < n) {
        int b = ls[i];
        unsigned act = __activemask();
        unsigned m = __match_any_sync(act, b);
        int lane = t & 31;
        int leader = __ffs(m) - 1;
        int rank = __popc(m & ((1u << lane) - 1u));
        int base = 0;
        if (lane == leader) base = atomicAdd(&cur[b], __popc(m));
        base = __shfl_sync(act, base, leader);
        g_order[base + rank] = i;
    }
}

// ---------------- main: 64-sample full-K CTAs, 2/SM, inline tail ----------------
// smem words: ws 12288 | xs 3*2304=6912 | sidx 64  => 19264 (77056 B)
#define XBUF_WORDS (CTA_S * XST)                   // 2304
#define SIDX_OFF (12288 + NSTAGE * XBUF_WORDS)     // 19200
#define SMEM_WORDS (SIDX_OFF + 64)                 // 19264
#define SMEM_BYTES (SMEM_WORDS * 4)

__device__ __forceinline__ unsigned smem_u32(const void* p) {
    unsigned a;
    asm("{ .reg .u64 t; cvta.to.shared.u64 t, %1; cvt.u32.u64 %0, t; }" : "=r"(a) : "l"(p));
    return a;
}

__global__ void __launch_bounds__(THREADS, 2) k_main(const float* __restrict__ x,
                                                     const float* __restrict__ b2,
                                                     const float* __restrict__ Wo,
                                                     const float* __restrict__ bo,
                                                     float* __restrict__ out) {
    extern __shared__ float sm[];
    float* ws   = sm;                    // 48KB weight sub-block
    float* xs   = ws + 12288;            // 3 x XBUF
    int* sidx_s = (int*)(sm + SIDX_OFF); // 64

    int tid = threadIdx.x;
    int base = blockIdx.x * CTA_S;
    if (base >= g_aoff[COUNT]) return;

    int b = 0;
#pragma unroll
    for (int t = 1; t < COUNT; ++t)
        if (base >= g_aoff[t]) b = t;

    if (tid < 64) sidx_s[tid] = g_order[base + tid];
    __syncthreads();

    // ---- async loader: 2 regions, idx = tid+256r -> row idx>>3, float4 idx&7 ----
    const char* gsrc[2];
    unsigned dsmem[2];
    unsigned xs_u = smem_u32(xs);
#pragma unroll
    for (int r = 0; r < 2; ++r) {
        int idx = tid + THREADS * r;
        int s = idx >> 3;                // 0..63
        int k4 = idx & 7;
        int sv = sidx_s[s];
        gsrc[r] = (const char*)(x + (size_t)(sv >= 0 ? sv : 0) * DIN + k4 * 4);
        dsmem[r] = xs_u + (unsigned)((s * XST + k4 * 4) * 4);
    }
#define ISSUE_CHUNK(c)                                                              \
    do {                                                                            \
        unsigned boff = (unsigned)(((c) % NSTAGE) * XBUF_WORDS * 4);                \
        _Pragma("unroll")                                                           \
        for (int r = 0; r < 2; ++r)                                                 \
            asm volatile("cp.async.cg.shared.global [%0], [%1], 16;"                \
                         :: "r"(dsmem[r] + boff), "l"(gsrc[r] + (size_t)(c) * 128)); \
        asm volatile("cp.async.commit_group;");                                     \
    } while (0)

    ISSUE_CHUNK(0);
    ISSUE_CHUNK(1);

    // ---- stage weight sub-block 0 (48 KB) ----
    {
        const float4* src = (const float4*)(g_wsum + (size_t)b * (DIN * L1N));
        float4* dst = (float4*)ws;
#pragma unroll
        for (int r = 0; r < 12; ++r) dst[tid + r * THREADS] = src[tid + r * THREADS];
    }

    int wid = tid >> 5, lane = tid & 31;
    int s0 = lane, s1 = lane + 32;

    unsigned long long acc[16];
#pragma unroll
    for (int i = 0; i < 16; ++i) acc[i] = 0ULL;

    const ulonglong2* wp = (const ulonglong2*)ws;

#pragma unroll 1
    for (int c = 0; c < NCHF; ++c) {
        if (c + 1 < NCHF) asm volatile("cp.async.wait_group 1;");
        else              asm volatile("cp.async.wait_group 0;");
        __syncthreads();
        if (c + 2 < NCHF) ISSUE_CHUNK(c + 2);
        if (c == WSUB) {
            // restage sub-block 1; all warps past chunk WSUB-1 due to barrier above
            const float4* src = (const float4*)(g_wsum + (size_t)b * (DIN * L1N) + (size_t)WSUB * CK * L1N);
            float4* dst = (float4*)ws;
#pragma unroll
            for (int r = 0; r < 12; ++r) dst[tid + r * THREADS] = src[tid + r * THREADS];
            __syncthreads();
        }

        const float* xb = xs + (c % NSTAGE) * XBUF_WORDS;
        float4 xa = *(const float4*)(xb + s0 * XST + wid * 4);
        float4 xc = *(const float4*)(xb + s1 * XST + wid * 4);
        int kg = (c % WSUB) * CK + wid * 4;
#pragma unroll
        for (int t4 = 0; t4 < 4; ++t4) {
            const ulonglong2* wr = wp + (unsigned)(kg + t4) * 4;
            ulonglong2 w0 = wr[0], w1 = wr[1], w2 = wr[2], w3 = wr[3];
            float va = (t4 == 0) ? xa.x : (t4 == 1) ? xa.y : (t4 == 2) ? xa.z : xa.w;
            float vc = (t4 == 0) ? xc.x : (t4 == 1) ? xc.y : (t4 == 2) ? xc.z : xc.w;
            unsigned long long da, dc;
            asm("mov.b64 %0, {%1, %1};" : "=l"(da) : "f"(va));
            asm("mov.b64 %0, {%1, %1};" : "=l"(dc) : "f"(vc));
            asm("fma.rn.f32x2 %0, %1, %2, %0;" : "+l"(acc[0]) : "l"(da), "l"(w0.x));
            asm("fma.rn.f32x2 %0, %1, %2, %0;" : "+l"(acc[1]) : "l"(da), "l"(w0.y));
            asm("fma.rn.f32x2 %0, %1, %2, %0;" : "+l"(acc[2]) : "l"(da), "l"(w1.x));
            asm("fma.rn.f32x2 %0, %1, %2, %0;" : "+l"(acc[3]) : "l"(da), "l"(w1.y));
            asm("fma.rn.f32x2 %0, %1, %2, %0;" : "+l"(acc[4]) : "l"(da), "l"(w2.x));
            asm("fma.rn.f32x2 %0, %1, %2, %0;" : "+l"(acc[5]) : "l"(da), "l"(w2.y));
            asm("fma.rn.f32x2 %0, %1, %2, %0;" : "+l"(acc[6]) : "l"(da), "l"(w3.x));
            asm("fma.rn.f32x2 %0, %1, %2, %0;" : "+l"(acc[7]) : "l"(da), "l"(w3.y));
            asm("fma.rn.f32x2 %0, %1, %2, %0;" : "+l"(acc[8])  : "l"(dc), "l"(w0.x));
            asm("fma.rn.f32x2 %0, %1, %2, %0;" : "+l"(acc[9])  : "l"(dc), "l"(w0.y));
            asm("fma.rn.f32x2 %0, %1, %2, %0;" : "+l"(acc[10]) : "l"(dc), "l"(w1.x));
            asm("fma.rn.f32x2 %0, %1, %2, %0;" : "+l"(acc[11]) : "l"(dc), "l"(w1.y));
            asm("fma.rn.f32x2 %0, %1, %2, %0;" : "+l"(acc[12]) : "l"(dc), "l"(w2.x));
            asm("fma.rn.f32x2 %0, %1, %2, %0;" : "+l"(acc[13]) : "l"(dc), "l"(w2.y));
            asm("fma.rn.f32x2 %0, %1, %2, %0;" : "+l"(acc[14]) : "l"(dc), "l"(w3.x));
            asm("fma.rn.f32x2 %0, %1, %2, %0;" : "+l"(acc[15]) : "l"(dc), "l"(w3.y));
        }
    }
    __syncthreads();

    // ---- 8-slice reduction (words 0..10239, inside ws) ----
    float* red = sm;
    {
        float* br0 = red + (wid * CTA_S + s0) * RST;
        float* br1 = red + (wid * CTA_S + s1) * RST;
#pragma unroll
        for (int p = 0; p < 4; ++p) {
            float lo0, hi0, lo1, hi1;
            asm("mov.b64 {%0, %1}, %2;" : "=f"(lo0), "=f"(hi0) : "l"(acc[2 * p]));
            asm("mov.b64 {%0, %1}, %2;" : "=f"(lo1), "=f"(hi1) : "l"(acc[2 * p + 1]));
            *(float4*)(br0 + 4 * p) = make_float4(lo0, hi0, lo1, hi1);
            asm("mov.b64 {%0, %1}, %2;" : "=f"(lo0), "=f"(hi0) : "l"(acc[8 + 2 * p]));
            asm("mov.b64 {%0, %1}, %2;" : "=f"(lo1), "=f"(hi1) : "l"(acc[8 + 2 * p + 1]));
            *(float4*)(br1 + 4 * p) = make_float4(lo0, hi0, lo1, hi1);
        }
    }
    __syncthreads();

    // ---- inline tail: stage L2/L3 weights into xs region (words 12288..14735) ----
    float* w2s  = sm + 12288;   // 2048
    float* bs2  = sm + 14336;   // 16
    float* b2s  = sm + 14352;   // 64
    float* wos  = sm + 14416;   // 64
    float* red2 = sm + 14480;   // 256
    {
        const float4* src = (const float4*)(g_w2p + (size_t)b * (L3N * 32));
        ((float4*)w2s)[tid] = src[tid];
        ((float4*)w2s)[tid + 256] = src[tid + 256];
    }
    if (tid < 16) bs2[tid] = g_bsum[b * L1N + tid];
    else if (tid >= 32 && tid < 96) b2s[tid - 32] = b2[b * L3N + (tid - 32)];
    else if (tid >= 96 && tid < 160) wos[tid - 96] = Wo[b * L3N + (tid - 96)];
    __syncthreads();

    int s2 = tid & 63;
    int jg = tid >> 6;   // 4 j-groups of 16

    float l1[16];
#pragma unroll
    for (int o = 0; o < 16; o += 4) {
        float4 v = *(const float4*)(bs2 + o);
#pragma unroll
        for (int q = 0; q < 8; ++q) {
            float4 r4 = *(const float4*)(red + (q * CTA_S + s2) * RST + o);
            v.x += r4.x; v.y += r4.y; v.z += r4.z; v.w += r4.w;
        }
        l1[o] = v.x; l1[o + 1] = v.y; l1[o + 2] = v.z; l1[o + 3] = v.w;
    }

    const float C = 127.0f / 128.0f;
    float lx[32];
#pragma unroll
    for (int i = 0; i < 15; ++i) {
        float v = l1[i];
        float sq = (v * v) * C;
        lx[i]      = fminf(fmaxf(sq, 0.0f), 1.0f);
        lx[15 + i] = fminf(fmaxf(v, 0.0f), 1.0f);
    }
    lx[30] = 0.0f;
    lx[31] = 0.0f;

    float l3p = 0.0f;
#pragma unroll 4
    for (int jj = 0; jj < 16; jj += 2) {
        int j = jg * 16 + jj;
        const float4* wrA = (const float4*)(w2s + j * 32);
        const float4* wrB = (const float4*)(w2s + (j + 1) * 32);
        float sA0 = b2s[j], sA1 = 0.0f;
        float sB0 = b2s[j + 1], sB1 = 0.0f;
#pragma unroll
        for (int p = 0; p < 8; p += 2) {
            float4 a0 = wrA[p], a1 = wrA[p + 1];
            float4 c0 = wrB[p], c1 = wrB[p + 1];
            sA0 = fmaf(lx[4*p+0], a0.x, sA0); sA0 = fmaf(lx[4*p+1], a0.y, sA0);
            sA0 = fmaf(lx[4*p+2], a0.z, sA0); sA0 = fmaf(lx[4*p+3], a0.w, sA0);
            sA1 = fmaf(lx[4*p+4], a1.x, sA1); sA1 = fmaf(lx[4*p+5], a1.y, sA1);
            sA1 = fmaf(lx[4*p+6], a1.z, sA1); sA1 = fmaf(lx[4*p+7], a1.w, sA1);
            sB0 = fmaf(lx[4*p+0], c0.x, sB0); sB0 = fmaf(lx[4*p+1], c0.y, sB0);
            sB0 = fmaf(lx[4*p+2], c0.z, sB0); sB0 = fmaf(lx[4*p+3], c0.w, sB0);
            sB1 = fmaf(lx[4*p+4], c1.x, sB1); sB1 = fmaf(lx[4*p+5], c1.y, sB1);
            sB1 = fmaf(lx[4*p+6], c1.z, sB1); sB1 = fmaf(lx[4*p+7], c1.w, sB1);
        }
        float scA = fminf(fmaxf(sA0 + sA1, 0.0f), 1.0f);
        float scB = fminf(fmaxf(sB0 + sB1, 0.0f), 1.0f);
        l3p = fmaf(scA, wos[j], l3p);
        l3p = fmaf(scB, wos[j + 1], l3p);
    }
    red2[jg * 64 + s2] = l3p;
    __syncthreads();

    if (tid < 64) {
        int sv = sidx_s[tid];
        if (sv >= 0) {
            float l3 = red2[tid] + red2[64 + tid] + red2[128 + tid] + red2[192 + tid];
            out[sv] = l3 + bo[b] + l1[15];
        }
    }
}

// ---------------- launch ----------------
extern "C" void kernel_launch(void* const* d_in, const int* in_sizes, int n_in,
                              void* d_out, int out_size) {
    const float* x  = (const float*)d_in[0];
    const int*   ls = (const int*)d_in[1];
    const float* W1 = (const float*)d_in[2];
    const float* b1 = (const float*)d_in[3];
    const float* Wf = (const float*)d_in[4];
    const float* bf = (const float*)d_in[5];
    const float* W2 = (const float*)d_in[6];
    const float* b2 = (const float*)d_in[7];
    const float* Wo = (const float*)d_in[8];
    const float* bo = (const float*)d_in[9];
    float* out = (float*)d_out;
    int n = in_sizes[1];
    if (n > BMAX) n = BMAX;

    cudaFuncSetAttribute(k_main, cudaFuncAttributeMaxDynamicSharedMemorySize, SMEM_BYTES);

    int hb = (n + 255) / 256;
    k_prep<<<768, 256>>>(W1, b1, Wf, bf, W2, ls, n, hb);
    k_scatter<<<hb, 256>>>(ls, n, hb);

    int nblk = (n + CTA_S - 1) / CTA_S + COUNT;   // 264 for n=16384
    k_main<<<nblk, THREADS, SMEM_BYTES>>>(x, b2, Wo, bo, out);
}